// round 3
// baseline (speedup 1.0000x reference)
#include <cuda_runtime.h>
#include <math.h>

// ---------------- problem constants ----------------
#define HID 128
#define INP 320
#define CIN 448           // HID + INP
#define BATCH 8
#define IMH 64
#define IMW 128
#define PLANE (IMH*IMW)   // 8192

// tile: 4 rows x 32 cols = 128 pixels per block
#define TH 4
#define TW 32
#define TP (TH*TW)        // 128
#define KC 16             // channels per k-chunk

// ---------------- device scratch (static allocation: allowed) ----------------
__device__ float g_z [BATCH*HID*IMH*IMW];   // sigmoid(z-gate)
__device__ float g_rh[BATCH*HID*IMH*IMW];   // r*h
__device__ float g_wd [3][CIN*9];           // quantized depthwise weights [c][3][3]
__device__ float g_wpT[3][CIN*HID];         // quantized pointwise weights, transposed [c][o]

// ---------------- helpers ----------------
__device__ __forceinline__ unsigned long long pack2(float a, float b) {
    unsigned long long r;
    asm("mov.b64 %0, {%1, %2};" : "=l"(r)
        : "r"(__float_as_uint(a)), "r"(__float_as_uint(b)));
    return r;
}
__device__ __forceinline__ void fma2(unsigned long long& d,
                                     unsigned long long a,
                                     unsigned long long b) {
    asm("fma.rn.f32x2 %0, %1, %2, %0;" : "+l"(d) : "l"(a), "l"(b));
}
__device__ __forceinline__ float sigmoidf_(float v) {
    return 1.0f / (1.0f + expf(-v));
}

// ---------------- weight fake-quant prep ----------------
// brevitas-style per-tensor symmetric int8 fake quant:
//   scale = max(max|w|, 1e-8)/127 ; q = clip(rint(w/scale),-128,127)*scale
// One block per weight tensor. pw weights are transposed to [c][o].
__global__ void quant_prep_kernel(const float* wdz, const float* wpz,
                                  const float* wdr, const float* wpr,
                                  const float* wdq, const float* wpq) {
    const int which = blockIdx.x;
    const float* src = nullptr; int n = 0; float* dst_dw = nullptr; float* dst_pw = nullptr;
    switch (which) {
        case 0: src = wdz; n = CIN*9;   dst_dw = g_wd[0];  break;
        case 1: src = wpz; n = CIN*HID; dst_pw = g_wpT[0]; break;
        case 2: src = wdr; n = CIN*9;   dst_dw = g_wd[1];  break;
        case 3: src = wpr; n = CIN*HID; dst_pw = g_wpT[1]; break;
        case 4: src = wdq; n = CIN*9;   dst_dw = g_wd[2];  break;
        default:src = wpq; n = CIN*HID; dst_pw = g_wpT[2]; break;
    }
    __shared__ float red[256];
    __shared__ float s_scale;
    const int tid = threadIdx.x;
    float m = 0.0f;
    for (int i = tid; i < n; i += 256) m = fmaxf(m, fabsf(src[i]));
    red[tid] = m;
    __syncthreads();
    for (int s = 128; s > 0; s >>= 1) {
        if (tid < s) red[tid] = fmaxf(red[tid], red[tid + s]);
        __syncthreads();
    }
    if (tid == 0) s_scale = fmaxf(red[0], 1e-8f) / 127.0f;
    __syncthreads();
    const float scale = s_scale;
    for (int i = tid; i < n; i += 256) {
        float q = rintf(src[i] / scale);            // round-half-even == jnp.round
        q = fminf(fmaxf(q, -128.0f), 127.0f);
        const float v = q * scale;
        if (dst_dw) {
            dst_dw[i] = v;                          // [c][9] layout kept
        } else {
            const int o = i / CIN;                  // wp is [O][C]
            const int c = i - o * CIN;
            dst_pw[c * HID + o] = v;                // store transposed [c][o]
        }
    }
}

// ---------------- fused gate kernel ----------------
// MODE 0: z = sigmoid(pw(dw(hx)))           -> g_z
// MODE 1: rh = sigmoid(pw(dw(hx))) * h      -> g_rh
// MODE 2: out = (1-z)*h + z*tanh(pw(dw(rhx))) -> dout
template <int MODE>
__global__ void __launch_bounds__(256)
gate_kernel(const float* __restrict__ h, const float* __restrict__ x,
            const float* __restrict__ bd, const float* __restrict__ bp,
            float* __restrict__ dout) {
    // smem: input halo tile, dw results, pw weight chunk (doubles as epilogue stage)
    __shared__ __align__(16) float s_in[KC * 205];     // stride_k=205 (odd -> bank spread)
    __shared__ __align__(16) float s_dw[KC * TP];      // [k][p]
    __shared__ __align__(16) float s_wp[2080];         // [k][o] (KC*128=2048) / stage 16*129
    __shared__ float s_wd[KC * 9];

    const int tid = threadIdx.x;
    const int b  = blockIdx.z;
    const int y0 = blockIdx.y << 2;    // TH=4
    const int x0 = blockIdx.x << 5;    // TW=32

    const float* in0 = (MODE == 2) ? g_rh : h;   // first 128 channels
    const float* wpg = g_wpT[MODE];
    const float* wdg = g_wd[MODE];

    // GEMM thread mapping: out-pairs o = 2*og + 32*i (+d), pixels p = 8*pg + j
    const int og = tid & 15;
    const int pg = tid >> 4;

    unsigned long long acc[4][8];
#pragma unroll
    for (int i = 0; i < 4; i++)
#pragma unroll
        for (int j = 0; j < 8; j++) acc[i][j] = 0ULL;

    // dw thread mapping: one channel-in-chunk, one row, 8 consecutive cols
    const int dk  = tid >> 4;
    const int dg  = tid & 15;
    const int drr = dg >> 2;
    const int dcg = (dg & 3) << 3;

    for (int c0 = 0; c0 < CIN; c0 += KC) {
        __syncthreads();  // previous chunk's GEMM reads done before refill

        // --- stage pw weight chunk [KC][128] (coalesced float4) ---
        {
            const float4* s4 = reinterpret_cast<const float4*>(wpg + (c0 << 7));
            float4* d4 = reinterpret_cast<float4*>(s_wp);
            d4[tid]       = s4[tid];
            d4[tid + 256] = s4[tid + 256];
        }
        // --- stage dw weight chunk ---
        if (tid < KC * 9) s_wd[tid] = wdg[c0 * 9 + tid];

        // --- stage input tile + halo: KC x 6 x 34 (zero padded at borders) ---
        for (int idx = tid; idx < KC * 204; idx += 256) {
            const int k  = idx / 204;
            const int rm = idx - k * 204;
            const int yy = rm / 34;
            const int xx = rm - yy * 34;
            const int cg = c0 + k;
            const int gy = y0 + yy - 1;
            const int gx = x0 + xx - 1;
            float v = 0.0f;
            if ((unsigned)gy < (unsigned)IMH && (unsigned)gx < (unsigned)IMW) {
                const float* pl = (cg < HID)
                    ? (in0 + (((size_t)b * HID + cg) << 13))
                    : (x   + (((size_t)b * INP + (cg - HID)) << 13));
                v = pl[(gy << 7) + gx];
            }
            s_in[k * 205 + yy * 34 + xx] = v;
        }
        __syncthreads();

        // --- depthwise 3x3 (+ bias) for this chunk -> s_dw[k][p] ---
        {
            float w9[9];
#pragma unroll
            for (int j = 0; j < 9; j++) w9[j] = s_wd[dk * 9 + j];
            const float bdv = bd[c0 + dk];
            const float* ib = &s_in[dk * 205 + drr * 34 + dcg];
            float rin[3][10];
#pragma unroll
            for (int dy = 0; dy < 3; dy++)
#pragma unroll
                for (int xx = 0; xx < 10; xx++) rin[dy][xx] = ib[dy * 34 + xx];
            float o8[8];
#pragma unroll
            for (int c = 0; c < 8; c++) {
                float a = bdv;
#pragma unroll
                for (int dy = 0; dy < 3; dy++)
#pragma unroll
                    for (int dx = 0; dx < 3; dx++)
                        a = fmaf(w9[dy * 3 + dx], rin[dy][c + dx], a);
                o8[c] = a;
            }
            float4* dp = reinterpret_cast<float4*>(&s_dw[(dk << 7) + (drr << 5) + dcg]);
            dp[0] = make_float4(o8[0], o8[1], o8[2], o8[3]);
            dp[1] = make_float4(o8[4], o8[5], o8[6], o8[7]);
        }
        __syncthreads();

        // --- pointwise GEMM accumulate: packed f32x2 (out-pairs) ---
#pragma unroll
        for (int k = 0; k < KC; k++) {
            const float* wk = &s_wp[(k << 7) + (og << 1)];
            const unsigned long long w0 = *reinterpret_cast<const unsigned long long*>(wk);
            const unsigned long long w1 = *reinterpret_cast<const unsigned long long*>(wk + 32);
            const unsigned long long w2 = *reinterpret_cast<const unsigned long long*>(wk + 64);
            const unsigned long long w3 = *reinterpret_cast<const unsigned long long*>(wk + 96);
            const float* dkp = &s_dw[(k << 7) + (pg << 3)];
#pragma unroll
            for (int j = 0; j < 8; j++) {
                const float dv = dkp[j];
                const unsigned long long dd = pack2(dv, dv);
                fma2(acc[0][j], w0, dd);
                fma2(acc[1][j], w1, dd);
                fma2(acc[2][j], w2, dd);
                fma2(acc[3][j], w3, dd);
            }
        }
    }

    // ---------------- epilogue: stage through smem for coalesced stores ----------------
#pragma unroll
    for (int i = 0; i < 4; i++) {
#pragma unroll
        for (int d = 0; d < 2; d++) {
            __syncthreads();   // also guards s_wp reuse after final GEMM
#pragma unroll
            for (int j = 0; j < 8; j++) {
                const unsigned long long a = acc[i][j];
                const unsigned int bits = d ? (unsigned int)(a >> 32) : (unsigned int)a;
                s_wp[og * 129 + (pg << 3) + j] = __uint_as_float(bits);
            }
            __syncthreads();
#pragma unroll
            for (int it = 0; it < 8; it++) {
                const int e   = tid + (it << 8);
                const int ogs = e >> 7;
                const int p   = e & 127;
                const int c   = (i << 5) + (ogs << 1) + d;
                const float v = s_wp[ogs * 129 + p] + bp[c];
                const int pr = p >> 5, pc = p & 31;
                const int gidx = (((b << 7) + c) << 13) + ((y0 + pr) << 7) + (x0 + pc);
                if (MODE == 0) {
                    g_z[gidx] = sigmoidf_(v);
                } else if (MODE == 1) {
                    g_rh[gidx] = h[gidx] * sigmoidf_(v);
                } else {
                    const float zz = g_z[gidx];
                    const float hv = h[gidx];
                    dout[gidx] = fmaf(zz, tanhf(v) - hv, hv);   // (1-z)h + z*q
                }
            }
        }
    }
}

// ---------------- launch ----------------
extern "C" void kernel_launch(void* const* d_in, const int* in_sizes, int n_in,
                              void* d_out, int out_size) {
    const float* h   = (const float*)d_in[0];
    const float* x   = (const float*)d_in[1];
    const float* wdz = (const float*)d_in[2];
    const float* bdz = (const float*)d_in[3];
    const float* wpz = (const float*)d_in[4];
    const float* bpz = (const float*)d_in[5];
    const float* wdr = (const float*)d_in[6];
    const float* bdr = (const float*)d_in[7];
    const float* wpr = (const float*)d_in[8];
    const float* bpr = (const float*)d_in[9];
    const float* wdq = (const float*)d_in[10];
    const float* bdq = (const float*)d_in[11];
    const float* wpq = (const float*)d_in[12];
    const float* bpq = (const float*)d_in[13];
    float* out = (float*)d_out;

    quant_prep_kernel<<<6, 256>>>(wdz, wpz, wdr, wpr, wdq, wpq);

    dim3 grid(IMW / TW, IMH / TH, BATCH);   // (4, 16, 8) = 512 blocks
    gate_kernel<0><<<grid, 256>>>(h, x, bdz, bpz, nullptr);
    gate_kernel<1><<<grid, 256>>>(h, x, bdr, bpr, nullptr);
    gate_kernel<2><<<grid, 256>>>(h, x, bdq, bpq, out);
}

// round 4
// speedup vs baseline: 1.9521x; 1.9521x over previous
#include <cuda_runtime.h>
#include <math.h>

// ---------------- problem constants ----------------
#define HID 128
#define INP 320
#define CIN 448           // HID + INP
#define BATCH 8
#define IMH 64
#define IMW 128

// tile: 4 rows x 32 cols = 128 pixels per block
#define TH 4
#define TW 32
#define TP (TH*TW)        // 128
#define KC 16             // channels per k-chunk
#define NCHUNK (CIN/KC)   // 28

// ---------------- dynamic smem layout (floats) ----------------
// s_in  : 2 x KC x 205   (halo tile, stride 205; rows 6x34 used)
// s_wp  : 2 x KC x 128   (pw weight chunk, [k][o])
// s_dw  : KC x 128       (dw results [k][p])
// s_wd  : CIN x 9        (all dw weights, preloaded once)
#define OFF_IN0   0
#define OFF_IN1   (KC*205)
#define OFF_WP0   (2*KC*205)
#define OFF_WP1   (2*KC*205 + KC*128)
#define OFF_DW    (2*KC*205 + 2*KC*128)
#define OFF_WD    (2*KC*205 + 2*KC*128 + KC*128)
#define SMEM_FLOATS (2*KC*205 + 3*KC*128 + CIN*9)
#define SMEM_BYTES (SMEM_FLOATS*4)   // 66944

// ---------------- device scratch ----------------
__device__ float g_z [BATCH*HID*IMH*IMW];   // sigmoid(z-gate)
__device__ float g_rh[BATCH*HID*IMH*IMW];   // r*h
__device__ float g_wd [3][CIN*9];           // quantized dw weights [c][3][3]
__device__ float g_wpT[3][CIN*HID];         // quantized pw weights transposed [c][o]

// ---------------- helpers ----------------
__device__ __forceinline__ unsigned long long pack2(float a, float b) {
    unsigned long long r;
    asm("mov.b64 %0, {%1, %2};" : "=l"(r)
        : "r"(__float_as_uint(a)), "r"(__float_as_uint(b)));
    return r;
}
__device__ __forceinline__ void fma2(unsigned long long& d,
                                     unsigned long long a,
                                     unsigned long long b) {
    asm("fma.rn.f32x2 %0, %1, %2, %0;" : "+l"(d) : "l"(a), "l"(b));
}
__device__ __forceinline__ float sigmoidf_(float v) {
    return 1.0f / (1.0f + expf(-v));
}
__device__ __forceinline__ void cpa4(unsigned int dst, const float* src, bool ok) {
    asm volatile("cp.async.ca.shared.global [%0], [%1], 4, %2;"
                 :: "r"(dst), "l"(src), "r"(ok ? 4 : 0) : "memory");
}
__device__ __forceinline__ void cpa16(unsigned int dst, const float* src) {
    asm volatile("cp.async.cg.shared.global [%0], [%1], 16;"
                 :: "r"(dst), "l"(src) : "memory");
}
__device__ __forceinline__ void cp_commit() {
    asm volatile("cp.async.commit_group;" ::: "memory");
}
__device__ __forceinline__ void cp_wait1() {
    asm volatile("cp.async.wait_group 1;" ::: "memory");
}

// ---------------- weight fake-quant prep ----------------
__global__ void quant_prep_kernel(const float* wdz, const float* wpz,
                                  const float* wdr, const float* wpr,
                                  const float* wdq, const float* wpq) {
    const int which = blockIdx.x;
    const float* src = nullptr; int n = 0; float* dst_dw = nullptr; float* dst_pw = nullptr;
    switch (which) {
        case 0: src = wdz; n = CIN*9;   dst_dw = g_wd[0];  break;
        case 1: src = wpz; n = CIN*HID; dst_pw = g_wpT[0]; break;
        case 2: src = wdr; n = CIN*9;   dst_dw = g_wd[1];  break;
        case 3: src = wpr; n = CIN*HID; dst_pw = g_wpT[1]; break;
        case 4: src = wdq; n = CIN*9;   dst_dw = g_wd[2];  break;
        default:src = wpq; n = CIN*HID; dst_pw = g_wpT[2]; break;
    }
    __shared__ float red[256];
    __shared__ float s_scale;
    const int tid = threadIdx.x;
    float m = 0.0f;
    for (int i = tid; i < n; i += 256) m = fmaxf(m, fabsf(src[i]));
    red[tid] = m;
    __syncthreads();
    for (int s = 128; s > 0; s >>= 1) {
        if (tid < s) red[tid] = fmaxf(red[tid], red[tid + s]);
        __syncthreads();
    }
    if (tid == 0) s_scale = fmaxf(red[0], 1e-8f) / 127.0f;
    __syncthreads();
    const float scale = s_scale;
    for (int i = tid; i < n; i += 256) {
        float q = rintf(src[i] / scale);            // round-half-even == jnp.round
        q = fminf(fmaxf(q, -128.0f), 127.0f);
        const float v = q * scale;
        if (dst_dw) {
            dst_dw[i] = v;
        } else {
            const int o = i / CIN;                  // wp is [O][C]
            const int c = i - o * CIN;
            dst_pw[c * HID + o] = v;                // store transposed [c][o]
        }
    }
}

// ---------------- fused gate kernel ----------------
// MODE 0: z = sigmoid(pw(dw(hx)))             -> g_z
// MODE 1: rh = sigmoid(pw(dw(hx))) * h        -> g_rh
// MODE 2: out = (1-z)*h + z*tanh(pw(dw(rhx))) -> dout
template <int MODE>
__global__ void __launch_bounds__(256, 2)
gate_kernel(const float* __restrict__ h, const float* __restrict__ x,
            const float* __restrict__ bd, const float* __restrict__ bp,
            float* __restrict__ dout) {
    extern __shared__ float smem[];
    float* s_dw = smem + OFF_DW;
    float* s_wd = smem + OFF_WD;
    const unsigned int smem_u32 = (unsigned int)__cvta_generic_to_shared(smem);

    const int tid = threadIdx.x;
    const int b  = blockIdx.z;
    const int y0 = blockIdx.y << 2;    // TH=4
    const int x0 = blockIdx.x << 5;    // TW=32

    const float* in0 = (MODE == 2) ? g_rh : h;   // first 128 channels
    const float* wpg = g_wpT[MODE];
    const float* wdg = g_wd[MODE];

    // staging thread mapping: one channel per 16-lane group
    const int kk  = tid >> 4;
    const int l16 = tid & 15;

    // GEMM thread mapping: out-pairs o = 2*og + 32*i (+d), pixels p = 8*pg + j
    const int og = tid & 15;
    const int pg = tid >> 4;

    // dw thread mapping
    const int dk  = tid >> 4;
    const int dg  = tid & 15;
    const int drr = dg >> 2;
    const int dcg = (dg & 3) << 3;

    unsigned long long acc[4][8];
#pragma unroll
    for (int i = 0; i < 4; i++)
#pragma unroll
        for (int j = 0; j < 8; j++) acc[i][j] = 0ULL;

    // ---- staging lambdas (manual) ----
    // input halo tile for chunk ci into buffer buf: KC x 6 x 34, zero-padded OOB
    auto stage_in = [&](int ci, int buf) {
        const int cg = ci * KC + kk;
        const float* pl = (cg < HID)
            ? (in0 + (((size_t)b * HID + cg) << 13))
            : (x   + (((size_t)b * INP + (cg - HID)) << 13));
        const unsigned int sb = smem_u32 + ((buf ? OFF_IN1 : OFF_IN0) + kk * 205) * 4;
#pragma unroll
        for (int row = 0; row < 6; row++) {
            const int gy = y0 + row - 1;
            const bool rok = (unsigned)gy < (unsigned)IMH;
#pragma unroll
            for (int s = 0; s < 3; s++) {
                const int xx = l16 + (s << 4);
                if (xx < 34) {
                    const int gx = x0 + xx - 1;
                    const bool ok = rok && ((unsigned)gx < (unsigned)IMW);
                    const int goff = ok ? ((gy << 7) + gx) : 0;
                    cpa4(sb + (row * 34 + xx) * 4, pl + goff, ok);
                }
            }
        }
    };
    auto stage_wp = [&](int ci, int buf) {
        const float* src = wpg + (ci << 11);  // KC*128 = 2048 floats per chunk
        const unsigned int db = smem_u32 + (buf ? OFF_WP1 : OFF_WP0) * 4;
        cpa16(db + tid * 16,          src + (tid << 2));
        cpa16(db + (tid + 256) * 16,  src + ((tid + 256) << 2));
    };

    // ---- prologue: all dw weights + chunk 0 ----
    {
        // CIN*9 = 4032 floats = 1008 float4
        const unsigned int db = smem_u32 + OFF_WD * 4;
#pragma unroll
        for (int t = 0; t < 4; t++) {
            const int i = tid + (t << 8);
            if (i < 1008) cpa16(db + i * 16, wdg + (i << 2));
        }
        stage_in(0, 0);
        stage_wp(0, 0);
        cp_commit();
    }

    for (int ci = 0; ci < NCHUNK; ci++) {
        const int buf = ci & 1;
        __syncthreads();                       // all warps done with gemm(ci-1)
        if (ci + 1 < NCHUNK) {
            stage_in(ci + 1, buf ^ 1);
            stage_wp(ci + 1, buf ^ 1);
        }
        cp_commit();                            // (possibly empty) group
        cp_wait1();                             // chunk ci's group complete
        __syncthreads();                        // visible to all threads

        const float* s_in_b = smem + (buf ? OFF_IN1 : OFF_IN0);
        const float* s_wp_b = smem + (buf ? OFF_WP1 : OFF_WP0);

        // --- depthwise 3x3 (+ bias) -> s_dw[k][p] ---
        {
            const int c0 = ci * KC;
            float w9[9];
#pragma unroll
            for (int j = 0; j < 9; j++) w9[j] = s_wd[(c0 + dk) * 9 + j];
            const float bdv = __ldg(&bd[c0 + dk]);
            const float* ib = &s_in_b[dk * 205 + drr * 34 + dcg];
            float rin[3][10];
#pragma unroll
            for (int dy = 0; dy < 3; dy++)
#pragma unroll
                for (int xx = 0; xx < 10; xx++) rin[dy][xx] = ib[dy * 34 + xx];
            float o8[8];
#pragma unroll
            for (int c = 0; c < 8; c++) {
                float a = bdv;
#pragma unroll
                for (int dy = 0; dy < 3; dy++)
#pragma unroll
                    for (int dx = 0; dx < 3; dx++)
                        a = fmaf(w9[dy * 3 + dx], rin[dy][c + dx], a);
                o8[c] = a;
            }
            float4* dp = reinterpret_cast<float4*>(&s_dw[(dk << 7) + (drr << 5) + dcg]);
            dp[0] = make_float4(o8[0], o8[1], o8[2], o8[3]);
            dp[1] = make_float4(o8[4], o8[5], o8[6], o8[7]);
        }
        __syncthreads();

        // --- pointwise GEMM accumulate: packed f32x2 (out-pairs) ---
#pragma unroll
        for (int k = 0; k < KC; k++) {
            const float* wk = &s_wp_b[(k << 7) + (og << 1)];
            const unsigned long long w0 = *reinterpret_cast<const unsigned long long*>(wk);
            const unsigned long long w1 = *reinterpret_cast<const unsigned long long*>(wk + 32);
            const unsigned long long w2 = *reinterpret_cast<const unsigned long long*>(wk + 64);
            const unsigned long long w3 = *reinterpret_cast<const unsigned long long*>(wk + 96);
            const float* dkp = &s_dw[(k << 7) + (pg << 3)];
            const float4 d0 = *reinterpret_cast<const float4*>(dkp);
            const float4 d1 = *reinterpret_cast<const float4*>(dkp + 4);
            const float dv8[8] = {d0.x, d0.y, d0.z, d0.w, d1.x, d1.y, d1.z, d1.w};
#pragma unroll
            for (int j = 0; j < 8; j++) {
                const unsigned long long dd = pack2(dv8[j], dv8[j]);
                fma2(acc[0][j], w0, dd);
                fma2(acc[1][j], w1, dd);
                fma2(acc[2][j], w2, dd);
                fma2(acc[3][j], w3, dd);
            }
        }
    }

    // ---------------- epilogue: stage through smem for coalesced stores ----------------
    float* s_ep = smem;   // reuse s_in region (needs 16*129 = 2064 floats)
#pragma unroll
    for (int i = 0; i < 4; i++) {
#pragma unroll
        for (int d = 0; d < 2; d++) {
            __syncthreads();
#pragma unroll
            for (int j = 0; j < 8; j++) {
                const unsigned long long a = acc[i][j];
                const unsigned int bits = d ? (unsigned int)(a >> 32) : (unsigned int)a;
                s_ep[og * 129 + (pg << 3) + j] = __uint_as_float(bits);
            }
            __syncthreads();
#pragma unroll
            for (int it = 0; it < 8; it++) {
                const int e   = tid + (it << 8);
                const int ogs = e >> 7;
                const int p   = e & 127;
                const int c   = (i << 5) + (ogs << 1) + d;
                const float v = s_ep[ogs * 129 + p] + __ldg(&bp[c]);
                const int pr = p >> 5, pc = p & 31;
                const int gidx = (((b << 7) + c) << 13) + ((y0 + pr) << 7) + (x0 + pc);
                if (MODE == 0) {
                    g_z[gidx] = sigmoidf_(v);
                } else if (MODE == 1) {
                    g_rh[gidx] = h[gidx] * sigmoidf_(v);
                } else {
                    const float zz = g_z[gidx];
                    const float hv = h[gidx];
                    dout[gidx] = fmaf(zz, tanhf(v) - hv, hv);   // (1-z)h + z*q
                }
            }
        }
    }
}

// ---------------- launch ----------------
extern "C" void kernel_launch(void* const* d_in, const int* in_sizes, int n_in,
                              void* d_out, int out_size) {
    const float* h   = (const float*)d_in[0];
    const float* x   = (const float*)d_in[1];
    const float* wdz = (const float*)d_in[2];
    const float* bdz = (const float*)d_in[3];
    const float* wpz = (const float*)d_in[4];
    const float* bpz = (const float*)d_in[5];
    const float* wdr = (const float*)d_in[6];
    const float* bdr = (const float*)d_in[7];
    const float* wpr = (const float*)d_in[8];
    const float* bpr = (const float*)d_in[9];
    const float* wdq = (const float*)d_in[10];
    const float* bdq = (const float*)d_in[11];
    const float* wpq = (const float*)d_in[12];
    const float* bpq = (const float*)d_in[13];
    float* out = (float*)d_out;

    cudaFuncSetAttribute(gate_kernel<0>, cudaFuncAttributeMaxDynamicSharedMemorySize, SMEM_BYTES);
    cudaFuncSetAttribute(gate_kernel<1>, cudaFuncAttributeMaxDynamicSharedMemorySize, SMEM_BYTES);
    cudaFuncSetAttribute(gate_kernel<2>, cudaFuncAttributeMaxDynamicSharedMemorySize, SMEM_BYTES);

    quant_prep_kernel<<<6, 256>>>(wdz, wpz, wdr, wpr, wdq, wpq);

    dim3 grid(IMW / TW, IMH / TH, BATCH);   // (4, 16, 8) = 512 blocks
    gate_kernel<0><<<grid, 256, SMEM_BYTES>>>(h, x, bdz, bpz, nullptr);
    gate_kernel<1><<<grid, 256, SMEM_BYTES>>>(h, x, bdr, bpr, nullptr);
    gate_kernel<2><<<grid, 256, SMEM_BYTES>>>(h, x, bdq, bpq, out);
}